// round 1
// baseline (speedup 1.0000x reference)
#include <cuda_runtime.h>
#include <cstdint>

#define B_   8
#define C_   256
#define H_   64
#define W_   64
#define N_   4096   // H*W
#define M_   1024   // (H/2)*(W/2)
#define HD_  64
#define NH_  4
#define EPSV 1e-5f

// ---------------- device scratch (static: no allocations allowed) ------------
__device__ float g_part[B_ * 64 * 2];          // stage-1 partial sum/sumsq
__device__ float g_s[B_ * C_];                 // per (b,c) norm scale
__device__ float g_t[B_ * C_];                 // per (b,c) norm bias
__device__ float g_xds[B_ * C_ * M_];          // avgpool(raw x)  [b][c][m]
__device__ float g_q [(size_t)B_ * C_ * N_];   // Q   [b][h*64+d][n]
__device__ float g_k [B_ * HD_ * M_];          // K   [b][d][m]
__device__ float g_v [B_ * M_ * HD_];          // V   [b][m][d]   (transposed)
__device__ float g_ao[(size_t)B_ * C_ * N_];   // attn out, channel-major

// ---------------- stage 1: per-batch partial reduction ----------------------
__global__ void reduce1(const float* __restrict__ x) {
    int b = blockIdx.y, chunk = blockIdx.x, t = threadIdx.x;
    const float4* p = (const float4*)(x + (size_t)b * C_ * N_ + (size_t)chunk * 16384);
    float s = 0.f, sq = 0.f;
#pragma unroll
    for (int i = 0; i < 16; i++) {
        float4 v = p[t + 256 * i];
        s  += v.x + v.y + v.z + v.w;
        sq += v.x * v.x + v.y * v.y + v.z * v.z + v.w * v.w;
    }
    __shared__ float ss[256], sq2[256];
    ss[t] = s; sq2[t] = sq;
    __syncthreads();
    for (int o = 128; o > 0; o >>= 1) {
        if (t < o) { ss[t] += ss[t + o]; sq2[t] += sq2[t + o]; }
        __syncthreads();
    }
    if (t == 0) {
        g_part[(b * 64 + chunk) * 2 + 0] = ss[0];
        g_part[(b * 64 + chunk) * 2 + 1] = sq2[0];
    }
}

// ---------------- stage 2: finalize stats, build per-(b,c) affine -----------
__global__ void reduce2(const float* __restrict__ gn_w, const float* __restrict__ gn_b) {
    int b = blockIdx.x, t = threadIdx.x;
    __shared__ float ss[64], sq2[64];
    if (t < 64) {
        ss[t]  = g_part[(b * 64 + t) * 2 + 0];
        sq2[t] = g_part[(b * 64 + t) * 2 + 1];
    }
    __syncthreads();
    for (int o = 32; o > 0; o >>= 1) {
        if (t < o) { ss[t] += ss[t + o]; sq2[t] += sq2[t + o]; }
        __syncthreads();
    }
    __shared__ float sh_mu, sh_inv;
    if (t == 0) {
        const float invN = 1.0f / (float)(C_ * N_);
        float mu  = ss[0] * invN;
        float var = sq2[0] * invN - mu * mu;
        sh_mu  = mu;
        sh_inv = rsqrtf(var + EPSV);
    }
    __syncthreads();
    float sc = sh_inv * gn_w[t];
    g_s[b * C_ + t] = sc;
    g_t[b * C_ + t] = gn_b[t] - sh_mu * sc;
}

// ---------------- avgpool 2x2 on RAW x (norm folded later) ------------------
__global__ void avgpool(const float* __restrict__ x) {
    int idx = blockIdx.x * 256 + threadIdx.x;   // < B*C*M
    int mw = idx & 31, mh = (idx >> 5) & 31, bc = idx >> 10;
    const float* p = x + (size_t)bc * N_ + (size_t)(mh * 2) * W_ + mw * 2;
    g_xds[idx] = 0.25f * (p[0] + p[1] + p[W_] + p[W_ + 1]);
}

// ---------------- generic batched SGEMM: C = A[M,K] * B[K,N] -----------------
// Optional: per-(batch,k) affine on B load (folded GroupNorm),
//           transposed store (for V), residual+gamma epilogue (for O proj).
__global__ void __launch_bounds__(256) gemm64(
    const float* __restrict__ A, const float* __restrict__ Bsrc, float* __restrict__ C,
    int M, int N, int K,
    long long strideB, long long strideC,
    const float* __restrict__ nsc, const float* __restrict__ nbias,
    int transStore,
    const float* __restrict__ resid, const float* __restrict__ gamma)
{
    int bz = blockIdx.z;
    const float* Bp = Bsrc + (size_t)bz * strideB;
    float* Cp = C + (size_t)bz * strideC;
    int m0 = blockIdx.y * 64, n0 = blockIdx.x * 64;
    int t = threadIdx.x, tx = t & 15, ty = t >> 4;

    __shared__ float As[16][68];   // [k][m], stride 68 keeps 16B alignment
    __shared__ float Bs[16][68];   // [k][n]

    float acc[4][4];
#pragma unroll
    for (int i = 0; i < 4; i++)
#pragma unroll
        for (int j = 0; j < 4; j++) acc[i][j] = 0.f;

    for (int k0 = 0; k0 < K; k0 += 16) {
        // A tile: 64 rows x 16 k, transpose into As[k][m]
        {
            int row = t >> 2, col4 = (t & 3) * 4;
            float4 av = *(const float4*)&A[(size_t)(m0 + row) * K + k0 + col4];
            As[col4 + 0][row] = av.x;
            As[col4 + 1][row] = av.y;
            As[col4 + 2][row] = av.z;
            As[col4 + 3][row] = av.w;
        }
        // B tile: 16 k x 64 n, with optional folded-norm affine
        {
            int kr = t >> 4, n4 = (t & 15) * 4;
            float4 bv = *(const float4*)&Bp[(size_t)(k0 + kr) * N + n0 + n4];
            if (nsc) {
                float sc = nsc[bz * K + k0 + kr];
                float tt = nbias[bz * K + k0 + kr];
                bv.x = fmaf(bv.x, sc, tt);
                bv.y = fmaf(bv.y, sc, tt);
                bv.z = fmaf(bv.z, sc, tt);
                bv.w = fmaf(bv.w, sc, tt);
            }
            *(float4*)&Bs[kr][n4] = bv;
        }
        __syncthreads();
#pragma unroll
        for (int k = 0; k < 16; k++) {
            float a[4], b[4];
#pragma unroll
            for (int i = 0; i < 4; i++) a[i] = As[k][ty * 4 + i];
#pragma unroll
            for (int j = 0; j < 4; j++) b[j] = Bs[k][tx * 4 + j];
#pragma unroll
            for (int i = 0; i < 4; i++)
#pragma unroll
                for (int j = 0; j < 4; j++) acc[i][j] = fmaf(a[i], b[j], acc[i][j]);
        }
        __syncthreads();
    }

    if (transStore) {
        // C[n][m] layout (ld = M)
#pragma unroll
        for (int i = 0; i < 4; i++)
#pragma unroll
            for (int j = 0; j < 4; j++)
                Cp[(size_t)(n0 + tx * 4 + j) * M + (m0 + ty * 4 + i)] = acc[i][j];
    } else if (resid) {
#pragma unroll
        for (int i = 0; i < 4; i++) {
            int m = m0 + ty * 4 + i;
            float g = gamma[m];
            size_t base = (size_t)m * N + n0 + tx * 4;
            float4 rv = *(const float4*)&resid[(size_t)bz * strideC + base];
            float4 ov;
            ov.x = rv.x + g * acc[i][0];
            ov.y = rv.y + g * acc[i][1];
            ov.z = rv.z + g * acc[i][2];
            ov.w = rv.w + g * acc[i][3];
            *(float4*)&Cp[base] = ov;
        }
    } else {
#pragma unroll
        for (int i = 0; i < 4; i++) {
            int m = m0 + ty * 4 + i;
            float4 ov;
            ov.x = acc[i][0]; ov.y = acc[i][1]; ov.z = acc[i][2]; ov.w = acc[i][3];
            *(float4*)&Cp[(size_t)m * N + n0 + tx * 4] = ov;
        }
    }
}

// ---------------- flash attention block: 64 queries, loop over 16 K-tiles ----
__global__ void __launch_bounds__(256) attn_kernel() {
    __shared__ float Qs[64][64];   // [d][j]
    __shared__ float KVs[64][64];  // K: [d][m]; later V: [m][d]
    __shared__ float Ps[64][64];   // probs [j][m]; epilogue reuse [d][j]

    int bh = blockIdx.y, b = bh >> 2, h = bh & 3;
    int n0 = blockIdx.x * 64;
    int t = threadIdx.x, tx = t & 15, ty = t >> 4;
    const float scale = 0.125f;    // hd^-0.5

    const float* qb = g_q + (size_t)b * C_ * N_ + (size_t)h * HD_ * N_ + n0;
#pragma unroll
    for (int it = 0; it < 4; it++) {
        int e = t + 256 * it, d = e >> 4, j4 = (e & 15) * 4;
        float4 v = *(const float4*)&qb[(size_t)d * N_ + j4];
        v.x *= scale; v.y *= scale; v.z *= scale; v.w *= scale;
        *(float4*)&Qs[d][j4] = v;
    }

    float mrun[4], lrun[4], Oacc[4][4];
#pragma unroll
    for (int i = 0; i < 4; i++) {
        mrun[i] = -1e30f; lrun[i] = 0.f;
#pragma unroll
        for (int j = 0; j < 4; j++) Oacc[i][j] = 0.f;
    }

    const float* kb = g_k + (size_t)b * HD_ * M_;
    const float* vb = g_v + (size_t)b * M_ * HD_;
    __syncthreads();

    for (int m0 = 0; m0 < M_; m0 += 64) {
        // K tile -> KVs[d][m]
#pragma unroll
        for (int it = 0; it < 4; it++) {
            int e = t + 256 * it, d = e >> 4, m4 = (e & 15) * 4;
            *(float4*)&KVs[d][m4] = *(const float4*)&kb[(size_t)d * M_ + m0 + m4];
        }
        __syncthreads();

        // S = Q K^T (64x64 tile), each thread 4x4
        float S[4][4];
#pragma unroll
        for (int i = 0; i < 4; i++)
#pragma unroll
            for (int j = 0; j < 4; j++) S[i][j] = 0.f;
#pragma unroll 8
        for (int d = 0; d < 64; d++) {
            float a[4], bb[4];
#pragma unroll
            for (int i = 0; i < 4; i++) a[i] = Qs[d][ty * 4 + i];
#pragma unroll
            for (int j = 0; j < 4; j++) bb[j] = KVs[d][tx * 4 + j];
#pragma unroll
            for (int i = 0; i < 4; i++)
#pragma unroll
                for (int j = 0; j < 4; j++) S[i][j] = fmaf(a[i], bb[j], S[i][j]);
        }

        // online softmax per row (16-lane shuffle groups share a row set)
        float fscale[4];
#pragma unroll
        for (int i = 0; i < 4; i++) {
            float mt = fmaxf(fmaxf(S[i][0], S[i][1]), fmaxf(S[i][2], S[i][3]));
#pragma unroll
            for (int o = 8; o >= 1; o >>= 1)
                mt = fmaxf(mt, __shfl_xor_sync(0xffffffffu, mt, o));
            float mnew = fmaxf(mrun[i], mt);
            float f = __expf(mrun[i] - mnew);
            float ls = 0.f;
#pragma unroll
            for (int j = 0; j < 4; j++) {
                S[i][j] = __expf(S[i][j] - mnew);
                ls += S[i][j];
            }
#pragma unroll
            for (int o = 8; o >= 1; o >>= 1)
                ls += __shfl_xor_sync(0xffffffffu, ls, o);
            lrun[i] = lrun[i] * f + ls;
            mrun[i] = mnew;
            fscale[i] = f;
        }
        // write P, rescale O accumulators
#pragma unroll
        for (int i = 0; i < 4; i++) {
            float4 pv; pv.x = S[i][0]; pv.y = S[i][1]; pv.z = S[i][2]; pv.w = S[i][3];
            *(float4*)&Ps[ty * 4 + i][tx * 4] = pv;
#pragma unroll
            for (int j = 0; j < 4; j++) Oacc[i][j] *= fscale[i];
        }
        __syncthreads();   // P visible; done reading K from KVs

        // V tile -> KVs[m][d]  (g_v already stored [m][d])
#pragma unroll
        for (int it = 0; it < 4; it++) {
            int e = t + 256 * it, m = e >> 4, d4 = (e & 15) * 4;
            *(float4*)&KVs[m][d4] = *(const float4*)&vb[(size_t)(m0 + m) * HD_ + d4];
        }
        __syncthreads();

        // O += P * V
#pragma unroll 8
        for (int m = 0; m < 64; m++) {
            float a[4], bb[4];
#pragma unroll
            for (int i = 0; i < 4; i++) a[i] = Ps[ty * 4 + i][m];
#pragma unroll
            for (int j = 0; j < 4; j++) bb[j] = KVs[m][tx * 4 + j];
#pragma unroll
            for (int i = 0; i < 4; i++)
#pragma unroll
                for (int j = 0; j < 4; j++) Oacc[i][j] = fmaf(a[i], bb[j], Oacc[i][j]);
        }
        __syncthreads();   // before next K-tile overwrites KVs / Ps
    }

    // normalize + transpose into Ps[d][j], then coalesced global store
    float linv[4];
#pragma unroll
    for (int i = 0; i < 4; i++) linv[i] = 1.0f / lrun[i];
#pragma unroll
    for (int i = 0; i < 4; i++)
#pragma unroll
        for (int j = 0; j < 4; j++)
            Ps[tx * 4 + j][ty * 4 + i] = Oacc[i][j] * linv[i];
    __syncthreads();

    float* ob = g_ao + (size_t)b * C_ * N_ + (size_t)h * HD_ * N_ + n0;
#pragma unroll
    for (int it = 0; it < 4; it++) {
        int e = t + 256 * it, d = e >> 4, j4 = (e & 15) * 4;
        *(float4*)&ob[(size_t)d * N_ + j4] = *(const float4*)&Ps[d][j4];
    }
}

// ---------------- launch ------------------------------------------------------
extern "C" void kernel_launch(void* const* d_in, const int* in_sizes, int n_in,
                              void* d_out, int out_size) {
    const float* x    = (const float*)d_in[0];
    const float* gn_w = (const float*)d_in[1];
    const float* gn_b = (const float*)d_in[2];
    const float* wq   = (const float*)d_in[3];
    const float* wk   = (const float*)d_in[4];
    const float* wv   = (const float*)d_in[5];
    const float* wo   = (const float*)d_in[6];
    const float* gamma= (const float*)d_in[7];
    float* out = (float*)d_out;

    float *pq, *pk, *pv, *pao, *pxds, *ps, *pt;
    cudaGetSymbolAddress((void**)&pq,   g_q);
    cudaGetSymbolAddress((void**)&pk,   g_k);
    cudaGetSymbolAddress((void**)&pv,   g_v);
    cudaGetSymbolAddress((void**)&pao,  g_ao);
    cudaGetSymbolAddress((void**)&pxds, g_xds);
    cudaGetSymbolAddress((void**)&ps,   g_s);
    cudaGetSymbolAddress((void**)&pt,   g_t);

    reduce1<<<dim3(64, 8), 256>>>(x);
    reduce2<<<8, 256>>>(gn_w, gn_b);
    avgpool<<<(B_ * C_ * M_) / 256, 256>>>(x);

    // Q = wq @ norm(x):  [256,4096] per batch
    gemm64<<<dim3(64, 4, 8), 256>>>(wq, x, pq, 256, 4096, 256,
                                    (long long)C_ * N_, (long long)C_ * N_,
                                    ps, pt, 0, nullptr, nullptr);
    // K = wk @ norm(avgpool(x)):  [64,1024] per batch
    gemm64<<<dim3(16, 1, 8), 256>>>(wk, pxds, pk, 64, 1024, 256,
                                    (long long)C_ * M_, (long long)HD_ * M_,
                                    ps, pt, 0, nullptr, nullptr);
    // V (stored transposed [m][d])
    gemm64<<<dim3(16, 1, 8), 256>>>(wv, pxds, pv, 64, 1024, 256,
                                    (long long)C_ * M_, (long long)M_ * HD_,
                                    ps, pt, 1, nullptr, nullptr);

    attn_kernel<<<dim3(64, 32), 256>>>();

    // out = x + gamma * (wo @ attn_out)
    gemm64<<<dim3(64, 4, 8), 256>>>(wo, pao, out, 256, 4096, 256,
                                    (long long)C_ * N_, (long long)C_ * N_,
                                    nullptr, nullptr, 0, x, gamma);
}

// round 5
// speedup vs baseline: 5.4020x; 5.4020x over previous
#include <cuda_runtime.h>
#include <cuda_bf16.h>
#include <cstdint>

#define B_   8
#define C_   256
#define N_   4096
#define M_   1024
#define HD_  64
#define EPSV 1e-5f

// ===================== helpers =====================
__device__ __forceinline__ uint32_t smem_u32(const void* p) {
    uint32_t a;
    asm("{ .reg .u64 tmp; cvta.to.shared.u64 tmp, %1; cvt.u32.u64 %0, tmp; }" : "=r"(a) : "l"(p));
    return a;
}
__device__ __forceinline__ void ldmx4(uint32_t r[4], uint32_t addr) {
    asm volatile("ldmatrix.sync.aligned.m8n8.x4.shared.b16 {%0,%1,%2,%3}, [%4];"
                 : "=r"(r[0]), "=r"(r[1]), "=r"(r[2]), "=r"(r[3]) : "r"(addr));
}
__device__ __forceinline__ void mma16816(float c[4], const uint32_t a[4], uint32_t b0, uint32_t b1) {
    asm volatile("mma.sync.aligned.m16n8k16.row.col.f32.bf16.bf16.f32 "
                 "{%0,%1,%2,%3}, {%4,%5,%6,%7}, {%8,%9}, {%0,%1,%2,%3};"
                 : "+f"(c[0]), "+f"(c[1]), "+f"(c[2]), "+f"(c[3])
                 : "r"(a[0]), "r"(a[1]), "r"(a[2]), "r"(a[3]), "r"(b0), "r"(b1));
}
__device__ __forceinline__ float ex2f(float x) {
    float r; asm("ex2.approx.ftz.f32 %0, %1;" : "=f"(r) : "f"(x)); return r;
}
__device__ __forceinline__ uint32_t pack_bf16x2(float lo, float hi) {
    uint32_t r;
    asm("cvt.rn.satfinite.bf16x2.f32 %0, %1, %2;" : "=r"(r) : "f"(hi), "f"(lo));
    return r;
}

// ===================== device scratch =====================
__device__ float g_part[B_ * 64 * 2];
__device__ float g_s[B_ * C_];
__device__ float g_t[B_ * C_];
__device__ __nv_bfloat16 g_xt [(size_t)B_ * N_ * C_];   // normalized, [b][n][c]
__device__ __nv_bfloat16 g_xds[(size_t)B_ * M_ * C_];   // pooled+norm, [b][m][c]
__device__ __nv_bfloat16 g_wqb[C_ * C_];
__device__ __nv_bfloat16 g_wkb[HD_ * C_];
__device__ __nv_bfloat16 g_wvb[HD_ * C_];
__device__ __nv_bfloat16 g_wob[C_ * C_];
__device__ __nv_bfloat16 g_qt [(size_t)B_ * N_ * C_];   // Q, [b][n][c]  (pre-scaled by hd^-.5*log2e)
__device__ __nv_bfloat16 g_kt [B_ * M_ * HD_];          // K, [b][m][d]
__device__ __nv_bfloat16 g_vt [B_ * HD_ * M_];          // V, [b][d][m]
__device__ __nv_bfloat16 g_ao [(size_t)B_ * N_ * C_];   // attn out, [b][n][c]

// ===================== stats =====================
__global__ void reduce1(const float* __restrict__ x) {
    int b = blockIdx.y, chunk = blockIdx.x, t = threadIdx.x;
    const float4* p = (const float4*)(x + (size_t)b * C_ * N_ + (size_t)chunk * 16384);
    float s = 0.f, sq = 0.f;
#pragma unroll
    for (int i = 0; i < 16; i++) {
        float4 v = p[t + 256 * i];
        s  += v.x + v.y + v.z + v.w;
        sq += v.x * v.x + v.y * v.y + v.z * v.z + v.w * v.w;
    }
    __shared__ float ss[256], sq2[256];
    ss[t] = s; sq2[t] = sq;
    __syncthreads();
    for (int o = 128; o > 0; o >>= 1) {
        if (t < o) { ss[t] += ss[t + o]; sq2[t] += sq2[t + o]; }
        __syncthreads();
    }
    if (t == 0) {
        g_part[(b * 64 + chunk) * 2 + 0] = ss[0];
        g_part[(b * 64 + chunk) * 2 + 1] = sq2[0];
    }
}
__global__ void reduce2(const float* __restrict__ gn_w, const float* __restrict__ gn_b) {
    int b = blockIdx.x, t = threadIdx.x;
    __shared__ float ss[64], sq2[64];
    if (t < 64) { ss[t] = g_part[(b * 64 + t) * 2]; sq2[t] = g_part[(b * 64 + t) * 2 + 1]; }
    __syncthreads();
    for (int o = 32; o > 0; o >>= 1) {
        if (t < o) { ss[t] += ss[t + o]; sq2[t] += sq2[t + o]; }
        __syncthreads();
    }
    __shared__ float sh_mu, sh_inv;
    if (t == 0) {
        const float invN = 1.0f / (float)(C_ * N_);
        float mu  = ss[0] * invN;
        float var = sq2[0] * invN - mu * mu;
        sh_mu = mu; sh_inv = rsqrtf(var + EPSV);
    }
    __syncthreads();
    float sc = sh_inv * gn_w[t];
    g_s[b * C_ + t] = sc;
    g_t[b * C_ + t] = gn_b[t] - sh_mu * sc;
}

// ===================== prep: normalize + transpose to bf16 =====================
__global__ void prep_xt(const float* __restrict__ x) {
    __shared__ float sm[32][33];
    int b = blockIdx.z, c0 = blockIdx.y * 32, n0 = blockIdx.x * 32;
    int tx = threadIdx.x, ty = threadIdx.y;
#pragma unroll
    for (int k = 0; k < 4; k++) {
        int c = c0 + ty + 8 * k;
        float v = x[((size_t)(b * C_ + c)) * N_ + n0 + tx];
        sm[ty + 8 * k][tx] = fmaf(v, g_s[b * C_ + c], g_t[b * C_ + c]);
    }
    __syncthreads();
#pragma unroll
    for (int k = 0; k < 4; k++) {
        int n = n0 + ty + 8 * k;
        g_xt[((size_t)(b * N_ + n)) * C_ + c0 + tx] = __float2bfloat16(sm[tx][ty + 8 * k]);
    }
}
__global__ void prep_xds(const float* __restrict__ x) {
    __shared__ float sm[8][33];
    int b = blockIdx.z, c0 = blockIdx.y * 8, m0 = blockIdx.x * 32;
    int tx = threadIdx.x, ty = threadIdx.y;
    int m = m0 + tx, mh = m >> 5, mw = m & 31;
    int c = c0 + ty;
    const float* p = x + ((size_t)(b * C_ + c)) * N_ + (size_t)(mh * 2) * 64 + mw * 2;
    float v = 0.25f * (p[0] + p[1] + p[64] + p[65]);
    sm[ty][tx] = fmaf(v, g_s[b * C_ + c], g_t[b * C_ + c]);
    __syncthreads();
    int tid = ty * 32 + tx, cw = tid & 7, mw2 = tid >> 3;
    g_xds[((size_t)(b * M_ + m0 + mw2)) * C_ + c0 + cw] = __float2bfloat16(sm[cw][mw2]);
}
__global__ void cvt_w(__nv_bfloat16* dst, const float* __restrict__ src, int n, float scale) {
    int i = blockIdx.x * 256 + threadIdx.x;
    if (i < n) dst[i] = __float2bfloat16(src[i] * scale);
}

// ===================== projection GEMM: D[128,64-tile] = A[rows,256] @ W[N,256]^T =====
// 256 thr = 8 warps (4 m x 2 n). CTA tile 128(M) x 64(N), K chunks of 32.
// mode 0: bf16 out[row][N]; mode 1: bf16 out[col][M_] (V transpose);
// mode 2: fp32 out[b][col][4096] = x + gamma*D  (channel-major, via smem staging)
__global__ void __launch_bounds__(256) proj_mma(
    const __nv_bfloat16* __restrict__ A, const __nv_bfloat16* __restrict__ Bw,
    int rows, int N, int mode,
    __nv_bfloat16* __restrict__ outb, float* __restrict__ outf,
    const float* __restrict__ xres, const float* __restrict__ gamma)
{
    __shared__ __align__(16) char smraw[33792];
    __nv_bfloat16* As = (__nv_bfloat16*)smraw;             // [128][40]
    __nv_bfloat16* Bs = (__nv_bfloat16*)(smraw + 10240);   // [64][40]
    float* Cs = (float*)smraw;                              // [64][132] epilogue staging

    int t = threadIdx.x, lane = t & 31, wid = t >> 5;
    int wm = wid >> 1, wn = wid & 1;
    int b = blockIdx.z, row0 = blockIdx.x * 128, n0 = blockIdx.y * 64;
    int g = lane >> 2, qt = lane & 3;

    float acc[2][4][4];
#pragma unroll
    for (int mi = 0; mi < 2; mi++)
#pragma unroll
        for (int ni = 0; ni < 4; ni++)
#pragma unroll
            for (int e = 0; e < 4; e++) acc[mi][ni][e] = 0.f;

    const __nv_bfloat16* Ag = A + ((size_t)b * rows + row0) * 256;

    for (int k0 = 0; k0 < 256; k0 += 32) {
#pragma unroll
        for (int i = 0; i < 2; i++) {
            int idx = t + 256 * i;
            int r = idx >> 2, kc = (idx & 3) * 8;
            *(uint4*)(As + r * 40 + kc) = *(const uint4*)(Ag + (size_t)r * 256 + k0 + kc);
        }
        {
            int r = t >> 2, kc = (t & 3) * 8;
            *(uint4*)(Bs + r * 40 + kc) = *(const uint4*)(Bw + (size_t)(n0 + r) * 256 + k0 + kc);
        }
        __syncthreads();
#pragma unroll
        for (int k16 = 0; k16 < 32; k16 += 16) {
            uint32_t af[2][4];
#pragma unroll
            for (int mi = 0; mi < 2; mi++) {
                uint32_t addr = smem_u32(As + (wm * 32 + mi * 16 + (lane & 15)) * 40
                                         + k16 + (lane >> 4) * 8);
                ldmx4(af[mi], addr);
            }
#pragma unroll
            for (int np = 0; np < 2; np++) {
                uint32_t bfm[4];
                uint32_t addr = smem_u32(Bs + (wn * 32 + np * 16 + (lane & 7) + ((lane >> 4) & 1) * 8) * 40
                                         + k16 + ((lane >> 3) & 1) * 8);
                ldmx4(bfm, addr);
                mma16816(acc[0][np * 2 + 0], af[0], bfm[0], bfm[1]);
                mma16816(acc[0][np * 2 + 1], af[0], bfm[2], bfm[3]);
                mma16816(acc[1][np * 2 + 0], af[1], bfm[0], bfm[1]);
                mma16816(acc[1][np * 2 + 1], af[1], bfm[2], bfm[3]);
            }
        }
        __syncthreads();
    }

    if (mode == 0) {
#pragma unroll
        for (int mi = 0; mi < 2; mi++)
#pragma unroll
            for (int ni = 0; ni < 4; ni++) {
                int r = row0 + wm * 32 + mi * 16 + g;
                int col = n0 + wn * 32 + ni * 8 + 2 * qt;
                *(uint32_t*)(outb + ((size_t)b * rows + r) * N + col) =
                    pack_bf16x2(acc[mi][ni][0], acc[mi][ni][1]);
                *(uint32_t*)(outb + ((size_t)b * rows + r + 8) * N + col) =
                    pack_bf16x2(acc[mi][ni][2], acc[mi][ni][3]);
            }
    } else if (mode == 1) {
#pragma unroll
        for (int mi = 0; mi < 2; mi++)
#pragma unroll
            for (int ni = 0; ni < 4; ni++) {
                int r = row0 + wm * 32 + mi * 16 + g;
                int col = n0 + wn * 32 + ni * 8 + 2 * qt;
                outb[((size_t)b * HD_ + col)     * M_ + r]     = __float2bfloat16(acc[mi][ni][0]);
                outb[((size_t)b * HD_ + col + 1) * M_ + r]     = __float2bfloat16(acc[mi][ni][1]);
                outb[((size_t)b * HD_ + col)     * M_ + r + 8] = __float2bfloat16(acc[mi][ni][2]);
                outb[((size_t)b * HD_ + col + 1) * M_ + r + 8] = __float2bfloat16(acc[mi][ni][3]);
            }
    } else {
        // stage Cs[col][row] then coalesced channel-major store with residual
#pragma unroll
        for (int mi = 0; mi < 2; mi++)
#pragma unroll
            for (int ni = 0; ni < 4; ni++) {
                int rL = wm * 32 + mi * 16 + g;
                int cL = wn * 32 + ni * 8 + 2 * qt;
                Cs[cL * 132 + rL]           = acc[mi][ni][0];
                Cs[(cL + 1) * 132 + rL]     = acc[mi][ni][1];
                Cs[cL * 132 + rL + 8]       = acc[mi][ni][2];
                Cs[(cL + 1) * 132 + rL + 8] = acc[mi][ni][3];
            }
        __syncthreads();
#pragma unroll
        for (int i = 0; i < 8; i++) {
            int idx = t + 256 * i;
            int col = idx >> 5, r4 = (idx & 31) * 4;
            float4 v = *(float4*)&Cs[col * 132 + r4];
            size_t off = ((size_t)b * C_ + n0 + col) * (size_t)N_ + row0 + r4;
            float gch = gamma[n0 + col];
            float4 xr = *(const float4*)&xres[off];
            v.x = fmaf(gch, v.x, xr.x);
            v.y = fmaf(gch, v.y, xr.y);
            v.z = fmaf(gch, v.z, xr.z);
            v.w = fmaf(gch, v.w, xr.w);
            *(float4*)&outf[off] = v;
        }
    }
}

// ===================== attention: 128 q/CTA, 8 warps (16 q each), HMMA =====================
// S = Q(reg frags) @ K^T (ldmatrix), max-free exp2 softmax entirely in registers,
// P fed back as PV A-fragments without touching smem.
__global__ void __launch_bounds__(256) attn_mma() {
    __shared__ __align__(16) __nv_bfloat16 Ks[64 * 72];   // [m][d] pad 72
    __shared__ __align__(16) __nv_bfloat16 Vs[64 * 72];   // [d][m] pad 72

    int t = threadIdx.x, lane = t & 31, w = t >> 5;
    int g = lane >> 2, qt = lane & 3;
    int bh = blockIdx.y, b = bh >> 2, h = bh & 3;
    int n0 = blockIdx.x * 128;

    // Q fragments straight from global (mma A layout is 2-contiguous-bf16 per lane)
    uint32_t qf[4][4];
    const __nv_bfloat16* Qg = g_qt + ((size_t)b * N_ + n0 + w * 16) * C_ + h * HD_;
#pragma unroll
    for (int k16 = 0; k16 < 4; k16++) {
        qf[k16][0] = *(const uint32_t*)(Qg + (size_t)g * C_       + k16 * 16 + 2 * qt);
        qf[k16][1] = *(const uint32_t*)(Qg + (size_t)(g + 8) * C_ + k16 * 16 + 2 * qt);
        qf[k16][2] = *(const uint32_t*)(Qg + (size_t)g * C_       + k16 * 16 + 8 + 2 * qt);
        qf[k16][3] = *(const uint32_t*)(Qg + (size_t)(g + 8) * C_ + k16 * 16 + 8 + 2 * qt);
    }

    float oacc[8][4];
#pragma unroll
    for (int ni = 0; ni < 8; ni++)
#pragma unroll
        for (int e = 0; e < 4; e++) oacc[ni][e] = 0.f;
    float lsum0 = 0.f, lsum1 = 0.f;

    const __nv_bfloat16* Kg = g_kt + (size_t)b * M_ * HD_;
    const __nv_bfloat16* Vg = g_vt + (size_t)b * HD_ * M_;

    for (int m0 = 0; m0 < M_; m0 += 64) {
#pragma unroll
        for (int i = 0; i < 2; i++) {
            int idx = t + 256 * i;
            int r = idx >> 3, cc = (idx & 7) * 8;
            *(uint4*)(Ks + r * 72 + cc) = *(const uint4*)(Kg + (size_t)(m0 + r) * HD_ + cc);
            *(uint4*)(Vs + r * 72 + cc) = *(const uint4*)(Vg + (size_t)r * M_ + m0 + cc);
        }
        __syncthreads();

        // S (in log2 units; wq pre-scaled)
        float sacc[8][4];
#pragma unroll
        for (int ni = 0; ni < 8; ni++)
#pragma unroll
            for (int e = 0; e < 4; e++) sacc[ni][e] = 0.f;
#pragma unroll
        for (int k16 = 0; k16 < 4; k16++) {
#pragma unroll
            for (int np = 0; np < 4; np++) {
                uint32_t bfm[4];
                uint32_t addr = smem_u32(Ks + (np * 16 + (lane & 7) + ((lane >> 4) & 1) * 8) * 72
                                         + k16 * 16 + ((lane >> 3) & 1) * 8);
                ldmx4(bfm, addr);
                mma16816(sacc[np * 2 + 0], qf[k16], bfm[0], bfm[1]);
                mma16816(sacc[np * 2 + 1], qf[k16], bfm[2], bfm[3]);
            }
        }

        // exp2 + pack into PV A-fragments (no smem round-trip)
        uint32_t pa[4][4];
#pragma unroll
        for (int j = 0; j < 4; j++) {
            float e00 = ex2f(sacc[2 * j][0]),     e01 = ex2f(sacc[2 * j][1]);
            float e10 = ex2f(sacc[2 * j][2]),     e11 = ex2f(sacc[2 * j][3]);
            float f00 = ex2f(sacc[2 * j + 1][0]), f01 = ex2f(sacc[2 * j + 1][1]);
            float f10 = ex2f(sacc[2 * j + 1][2]), f11 = ex2f(sacc[2 * j + 1][3]);
            lsum0 += e00 + e01 + f00 + f01;
            lsum1 += e10 + e11 + f10 + f11;
            pa[j][0] = pack_bf16x2(e00, e01);
            pa[j][1] = pack_bf16x2(e10, e11);
            pa[j][2] = pack_bf16x2(f00, f01);
            pa[j][3] = pack_bf16x2(f10, f11);
        }

        // O += P @ V
#pragma unroll
        for (int k16 = 0; k16 < 4; k16++) {
#pragma unroll
            for (int np = 0; np < 4; np++) {
                uint32_t bfm[4];
                uint32_t addr = smem_u32(Vs + (np * 16 + (lane & 7) + ((lane >> 4) & 1) * 8) * 72
                                         + k16 * 16 + ((lane >> 3) & 1) * 8);
                ldmx4(bfm, addr);
                mma16816(oacc[np * 2 + 0], pa[k16], bfm[0], bfm[1]);
                mma16816(oacc[np * 2 + 1], pa[k16], bfm[2], bfm[3]);
            }
        }
        __syncthreads();
    }

    // row sums live in a quad (t = 0..3 cover all columns)
#pragma unroll
    for (int o = 1; o <= 2; o <<= 1) {
        lsum0 += __shfl_xor_sync(0xffffffffu, lsum0, o);
        lsum1 += __shfl_xor_sync(0xffffffffu, lsum1, o);
    }
    float inv0 = 1.0f / lsum0, inv1 = 1.0f / lsum1;

    __nv_bfloat16* Og = g_ao + ((size_t)b * N_ + n0 + w * 16) * C_ + h * HD_;
#pragma unroll
    for (int ni = 0; ni < 8; ni++) {
        int col = ni * 8 + 2 * qt;
        *(uint32_t*)(Og + (size_t)g * C_ + col) =
            pack_bf16x2(oacc[ni][0] * inv0, oacc[ni][1] * inv0);
        *(uint32_t*)(Og + (size_t)(g + 8) * C_ + col) =
            pack_bf16x2(oacc[ni][2] * inv1, oacc[ni][3] * inv1);
    }
}

// ===================== launch =====================
extern "C" void kernel_launch(void* const* d_in, const int* in_sizes, int n_in,
                              void* d_out, int out_size) {
    const float* x    = (const float*)d_in[0];
    const float* gn_w = (const float*)d_in[1];
    const float* gn_b = (const float*)d_in[2];
    const float* wq   = (const float*)d_in[3];
    const float* wk   = (const float*)d_in[4];
    const float* wv   = (const float*)d_in[5];
    const float* wo   = (const float*)d_in[6];
    const float* gamma= (const float*)d_in[7];
    float* out = (float*)d_out;

    __nv_bfloat16 *pxt, *pxds, *pwq, *pwk, *pwv, *pwo, *pqt, *pkt, *pvt, *pao;
    cudaGetSymbolAddress((void**)&pxt,  g_xt);
    cudaGetSymbolAddress((void**)&pxds, g_xds);
    cudaGetSymbolAddress((void**)&pwq,  g_wqb);
    cudaGetSymbolAddress((void**)&pwk,  g_wkb);
    cudaGetSymbolAddress((void**)&pwv,  g_wvb);
    cudaGetSymbolAddress((void**)&pwo,  g_wob);
    cudaGetSymbolAddress((void**)&pqt,  g_qt);
    cudaGetSymbolAddress((void**)&pkt,  g_kt);
    cudaGetSymbolAddress((void**)&pvt,  g_vt);
    cudaGetSymbolAddress((void**)&pao,  g_ao);

    reduce1<<<dim3(64, 8), 256>>>(x);
    reduce2<<<8, 256>>>(gn_w, gn_b);

    // wq folds hd^-0.5 * log2(e) so softmax is raw ex2
    cvt_w<<<256, 256>>>(pwq, wq, C_ * C_, 0.125f * 1.4426950408889634f);
    cvt_w<<<64, 256>>>(pwk, wk, HD_ * C_, 1.0f);
    cvt_w<<<64, 256>>>(pwv, wv, HD_ * C_, 1.0f);
    cvt_w<<<256, 256>>>(pwo, wo, C_ * C_, 1.0f);

    prep_xt<<<dim3(128, 8, 8), dim3(32, 8)>>>(x);
    prep_xds<<<dim3(32, 32, 8), dim3(32, 8)>>>(x);

    // Q = xt @ wq^T -> [b][n][256] bf16
    proj_mma<<<dim3(32, 4, 8), 256>>>(pxt, pwq, N_, 256, 0, pqt, nullptr, nullptr, nullptr);
    // K = xds @ wk^T -> [b][m][64] bf16
    proj_mma<<<dim3(8, 1, 8), 256>>>(pxds, pwk, M_, 64, 0, pkt, nullptr, nullptr, nullptr);
    // V = xds @ wv^T -> transposed [b][d][1024] bf16
    proj_mma<<<dim3(8, 1, 8), 256>>>(pxds, pwv, M_, 64, 1, pvt, nullptr, nullptr, nullptr);

    attn_mma<<<dim3(32, 32), 256>>>();

    // out = x + gamma * (ao @ wo^T), channel-major fp32
    proj_mma<<<dim3(32, 4, 8), 256>>>(pao, pwo, N_, 256, 2, nullptr, out, x, gamma);
}